// round 3
// baseline (speedup 1.0000x reference)
#include <cuda_runtime.h>
#include <math.h>

// ---------------------------------------------------------------------------
// Problem constants (fixed instance: B=4096, D=512). Scratch lives in
// __device__ globals (no allocations allowed); kernels reference the symbols
// directly so kernel_launch is pure kernel launches (graph-capture safe).
// ---------------------------------------------------------------------------
#define BMAX 4096
#define DMAX 512
#define TEMP_INV (1.0f / 0.07f)
#define MARGIN 0.2f

static __device__ float g_vn[BMAX * DMAX];                    // normalized vision
static __device__ float g_tn[BMAX * DMAX];                    // normalized text
static __device__ float g_sim[(size_t)BMAX * BMAX];           // sim = Vn Tn^T
static __device__ float g_simT[(size_t)BMAX * BMAX];          // sim^T
static __device__ float g_lossA[BMAX];                        // v2t per-row loss
static __device__ float g_lossB[BMAX];                        // t2v per-row loss
static __device__ float g_cnt[BMAX];                          // per-row positive count
static __device__ int   g_idmode;                             // 0 = int32 ids, 1 = int64 ids

// ---------------------------------------------------------------------------
// Reductions
// ---------------------------------------------------------------------------
__device__ __forceinline__ float warpSum(float v) {
#pragma unroll
    for (int o = 16; o; o >>= 1) v += __shfl_down_sync(0xffffffffu, v, o);
    return v;
}

__device__ __forceinline__ float blockSum(float v, float* sred, int nwarp) {
    v = warpSum(v);
    int w = threadIdx.x >> 5, l = threadIdx.x & 31;
    if (l == 0) sred[w] = v;
    __syncthreads();
    if (threadIdx.x < 32) {
        float x = (l < nwarp) ? sred[l] : 0.0f;
        x = warpSum(x);
        if (l == 0) sred[0] = x;
    }
    __syncthreads();
    float r = sred[0];
    __syncthreads();
    return r;
}

// ---------------------------------------------------------------------------
// 0. Detect match_ids dtype. jax without x64 downcasts the reference's int64
//    to int32; we cannot know which the harness handed us. If the buffer is
//    int64 (values < 2^31), the odd 32-bit words of the first B words are all
//    zero; if int32, roughly half are nonzero. Reads only B words = safe for
//    both layouts. Deterministic each launch.
// ---------------------------------------------------------------------------
__global__ __launch_bounds__(256) void k_detect(const int* __restrict__ w, int n) {
    __shared__ int flag;
    if (threadIdx.x == 0) flag = 0;
    __syncthreads();
    for (int j = threadIdx.x * 2 + 1; j < n; j += 512)
        if (w[j] != 0) flag = 1;   // benign race: any writer sets 1
    __syncthreads();
    if (threadIdx.x == 0) g_idmode = flag ? 0 : 1;
}

__device__ __forceinline__ long long load_id(const void* ids, int j, int mode) {
    return mode ? ((const long long*)ids)[j] : (long long)((const int*)ids)[j];
}

// ---------------------------------------------------------------------------
// 1. L2 normalize: one block (128 threads) per row. which = 0 -> vision->g_vn,
//    which = 1 -> text->g_tn.  out = x / max(||x||, 1e-12)
// ---------------------------------------------------------------------------
__global__ __launch_bounds__(128) void k_l2norm(const float* __restrict__ in,
                                                int D, int which) {
    __shared__ float sred[4];
    int row = blockIdx.x;
    float* out = which ? g_tn : g_vn;
    const float* r = in + (size_t)row * D;
    float* w = out + (size_t)row * D;
    float ss = 0.0f;
    for (int j = threadIdx.x * 4; j < D; j += 128 * 4) {
        float4 v = *(const float4*)&r[j];
        ss += v.x * v.x + v.y * v.y + v.z * v.z + v.w * v.w;
    }
    float tot = blockSum(ss, sred, 4);
    float inv = 1.0f / fmaxf(sqrtf(tot), 1e-12f);
    for (int j = threadIdx.x * 4; j < D; j += 128 * 4) {
        float4 v = *(const float4*)&r[j];
        v.x *= inv; v.y *= inv; v.z *= inv; v.w *= inv;
        *(float4*)&w[j] = v;
    }
}

// ---------------------------------------------------------------------------
// 2. SGEMM NT: g_sim[i][j] = dot(g_vn_i, g_tn_j). Tile 128x128x32,
//    256 threads, 8x8 per thread (strided mapping: row = ty+16u, col = tx+16v).
// ---------------------------------------------------------------------------
__global__ __launch_bounds__(256) void k_gemm_nt(int N, int D) {
    __shared__ float As[32][128];
    __shared__ float Bs[32][128];
    const float* __restrict__ A = g_vn;
    const float* __restrict__ Bm = g_tn;
    int tid = threadIdx.x;
    int tx = tid & 15, ty = tid >> 4;
    int row0 = blockIdx.y * 128, col0 = blockIdx.x * 128;

    float acc[8][8];
#pragma unroll
    for (int u = 0; u < 8; u++)
#pragma unroll
        for (int v = 0; v < 8; v++) acc[u][v] = 0.0f;

    for (int k0 = 0; k0 < D; k0 += 32) {
        // Load 128x32 tiles of A and B, transposed into smem (k-major rows).
#pragma unroll
        for (int q = 0; q < 4; q++) {
            int f = tid + q * 256;       // float4 index, 1024 total per matrix
            int r = f >> 3;              // row within tile (8 float4 per row)
            int kc = (f & 7) << 2;       // k offset
            float4 va = *(const float4*)&A[(size_t)(row0 + r) * D + k0 + kc];
            As[kc + 0][r] = va.x; As[kc + 1][r] = va.y;
            As[kc + 2][r] = va.z; As[kc + 3][r] = va.w;
            float4 vb = *(const float4*)&Bm[(size_t)(col0 + r) * D + k0 + kc];
            Bs[kc + 0][r] = vb.x; Bs[kc + 1][r] = vb.y;
            Bs[kc + 2][r] = vb.z; Bs[kc + 3][r] = vb.w;
        }
        __syncthreads();
#pragma unroll
        for (int k = 0; k < 32; k++) {
            float ra[8], rb[8];
#pragma unroll
            for (int u = 0; u < 8; u++) ra[u] = As[k][ty + 16 * u];
#pragma unroll
            for (int v = 0; v < 8; v++) rb[v] = Bs[k][tx + 16 * v];
#pragma unroll
            for (int u = 0; u < 8; u++)
#pragma unroll
                for (int v = 0; v < 8; v++) acc[u][v] += ra[u] * rb[v];
        }
        __syncthreads();
    }
#pragma unroll
    for (int u = 0; u < 8; u++) {
        int row = row0 + ty + 16 * u;
#pragma unroll
        for (int v = 0; v < 8; v++) {
            int col = col0 + tx + 16 * v;
            g_sim[(size_t)row * N + col] = acc[u][v];
        }
    }
}

// ---------------------------------------------------------------------------
// 3. Transpose g_sim -> g_simT (32x32 tiles, block 32x8)
// ---------------------------------------------------------------------------
__global__ __launch_bounds__(256) void k_transpose(int N) {
    __shared__ float tile[32][33];
    int x0 = blockIdx.x * 32, y0 = blockIdx.y * 32;
    int tx = threadIdx.x, ty = threadIdx.y;
#pragma unroll
    for (int j = 0; j < 4; j++)
        tile[ty + 8 * j][tx] = g_sim[(size_t)(y0 + ty + 8 * j) * N + x0 + tx];
    __syncthreads();
#pragma unroll
    for (int j = 0; j < 4; j++)
        g_simT[(size_t)(x0 + ty + 8 * j) * N + y0 + tx] = tile[tx][ty + 8 * j];
}

// ---------------------------------------------------------------------------
// 4. Directional loss: one block (256 threads) per anchor row.
//    dir = 0: read g_sim, write g_lossA and g_cnt
//    dir = 1: read g_simT, write g_lossB
// ---------------------------------------------------------------------------
__global__ __launch_bounds__(256) void k_loss(const void* __restrict__ ids,
                                              int N, int dir) {
    __shared__ float s_sim[BMAX];
    __shared__ unsigned char s_m[BMAX];
    __shared__ float sred[8];

    const float* sim = dir ? g_simT : g_sim;
    int row = blockIdx.x;
    int mode = g_idmode;
    long long myid = load_id(ids, row, mode);
    int tid = threadIdx.x;

    // Pass 1: load row into smem, build match mask, positive sum & count
    float psum = 0.0f, pcnt = 0.0f;
    for (int j = tid; j < N; j += 256) {
        float s = sim[(size_t)row * N + j];
        s_sim[j] = s;
        bool m = (load_id(ids, j, mode) == myid);
        s_m[j] = (unsigned char)m;
        if (m) { psum += s; pcnt += 1.0f; }
    }
    float psumT = blockSum(psum, sred, 8);
    float pcntT = blockSum(pcnt, sred, 8);
    float mean_pos = psumT / fmaxf(pcntT, 1.0f);

    // Pass 2: weighted negative exp sum (semi-hard negatives get weight 2)
    float neg = 0.0f;
    float lo = mean_pos - MARGIN;
    for (int j = tid; j < N; j += 256) {
        if (!s_m[j]) {
            float s = s_sim[j];
            float w = (s < mean_pos && s > lo) ? 2.0f : 1.0f;
            neg += __expf(s * TEMP_INV) * w;
        }
    }
    float negT = blockSum(neg, sred, 8);

    // Pass 3: per-positive loss terms: log1p(neg * exp(-s/T)) ==
    //         -log(exp(s/T) / (exp(s/T) + neg))   (numerically stable)
    float lsum = 0.0f;
    for (int j = tid; j < N; j += 256) {
        if (s_m[j]) lsum += log1pf(negT * __expf(-s_sim[j] * TEMP_INV));
    }
    float lsumT = blockSum(lsum, sred, 8);

    if (tid == 0) {
        // valid_row: has positives AND has at least one negative
        bool valid = (pcntT > 0.5f) && (pcntT < (float)N - 0.5f);
        float r = valid ? lsumT : 0.0f;
        if (dir == 0) { g_lossA[row] = r; g_cnt[row] = pcntT; }
        else          { g_lossB[row] = r; }
    }
}

// ---------------------------------------------------------------------------
// 5. Finalize: single block reduces partials to scalar loss
// ---------------------------------------------------------------------------
__global__ __launch_bounds__(256) void k_finalize(float* __restrict__ out, int N) {
    __shared__ float sred[8];
    float a = 0.0f, b = 0.0f, c = 0.0f;
    for (int i = threadIdx.x; i < N; i += 256) {
        a += g_lossA[i];
        b += g_lossB[i];
        c += g_cnt[i];
    }
    float sa = blockSum(a, sred, 8);
    float sb = blockSum(b, sred, 8);
    float sc = blockSum(c, sred, 8);
    if (threadIdx.x == 0) {
        float loss = (sc > 0.0f) ? (sa + sb) / (2.0f * fmaxf(sc, 1.0f)) : 0.0f;
        out[0] = loss;
    }
}

// ---------------------------------------------------------------------------
// Launch: pure kernel launches only (graph-capture safe, allocation-free)
// ---------------------------------------------------------------------------
extern "C" void kernel_launch(void* const* d_in, const int* in_sizes, int n_in,
                              void* d_out, int out_size) {
    const float* vis = (const float*)d_in[0];
    const float* txt = (const float*)d_in[1];
    const void* ids = d_in[2];
    float* out = (float*)d_out;

    int B = in_sizes[2];
    int D = in_sizes[0] / B;
    if (B > BMAX) B = BMAX;
    if (D > DMAX) D = DMAX;

    k_detect<<<1, 256>>>((const int*)ids, B);

    k_l2norm<<<B, 128>>>(vis, D, 0);
    k_l2norm<<<B, 128>>>(txt, D, 1);

    dim3 ggrid(B / 128, B / 128);
    k_gemm_nt<<<ggrid, 256>>>(B, D);

    dim3 tgrid(B / 32, B / 32);
    k_transpose<<<tgrid, dim3(32, 8)>>>(B);

    k_loss<<<B, 256>>>(ids, B, 0);
    k_loss<<<B, 256>>>(ids, B, 1);

    k_finalize<<<1, 256>>>(out, B);
}

// round 4
// speedup vs baseline: 2.4673x; 2.4673x over previous
#include <cuda_runtime.h>
#include <math.h>
#include <stdint.h>

// ---------------------------------------------------------------------------
// Problem constants (fixed instance: B=4096, D=512). Scratch lives in
// __device__ globals (no allocations allowed); kernels reference the symbols
// directly so kernel_launch is pure kernel launches (graph-capture safe).
// ---------------------------------------------------------------------------
#define BMAX 4096
#define DMAX 512
#define TEMP_INV (1.0f / 0.07f)
#define MARGIN 0.2f

static __device__ float g_vn[BMAX * DMAX];                    // normalized vision (tf32-rounded)
static __device__ float g_tn[BMAX * DMAX];                    // normalized text (tf32-rounded)
static __device__ float g_sim[(size_t)BMAX * BMAX];           // sim = Vn Tn^T
static __device__ float g_simT[(size_t)BMAX * BMAX];          // sim^T
static __device__ float g_lossA[BMAX];                        // v2t per-row loss
static __device__ float g_lossB[BMAX];                        // t2v per-row loss
static __device__ float g_cnt[BMAX];                          // per-row positive count
static __device__ int   g_idmode;                             // 0 = int32 ids, 1 = int64 ids

// ---------------------------------------------------------------------------
// Reductions
// ---------------------------------------------------------------------------
__device__ __forceinline__ float warpSum(float v) {
#pragma unroll
    for (int o = 16; o; o >>= 1) v += __shfl_down_sync(0xffffffffu, v, o);
    return v;
}

__device__ __forceinline__ float blockSum(float v, float* sred, int nwarp) {
    v = warpSum(v);
    int w = threadIdx.x >> 5, l = threadIdx.x & 31;
    if (l == 0) sred[w] = v;
    __syncthreads();
    if (threadIdx.x < 32) {
        float x = (l < nwarp) ? sred[l] : 0.0f;
        x = warpSum(x);
        if (l == 0) sred[0] = x;
    }
    __syncthreads();
    float r = sred[0];
    __syncthreads();
    return r;
}

// ---------------------------------------------------------------------------
// 0. Detect match_ids dtype (int64 reference may have been downcast to int32
//    by the jax pipeline). If int64 with values < 2^31, all odd 32-bit words
//    of the first n words are zero; if int32, roughly half are nonzero.
// ---------------------------------------------------------------------------
__global__ __launch_bounds__(256) void k_detect(const int* __restrict__ w, int n) {
    __shared__ int flag;
    if (threadIdx.x == 0) flag = 0;
    __syncthreads();
    for (int j = threadIdx.x * 2 + 1; j < n; j += 512)
        if (w[j] != 0) flag = 1;   // benign race: any writer sets 1
    __syncthreads();
    if (threadIdx.x == 0) g_idmode = flag ? 0 : 1;
}

__device__ __forceinline__ long long load_id(const void* ids, int j, int mode) {
    return mode ? ((const long long*)ids)[j] : (long long)((const int*)ids)[j];
}

// ---------------------------------------------------------------------------
// tf32 round-to-nearest helper
// ---------------------------------------------------------------------------
__device__ __forceinline__ float to_tf32(float x) {
    uint32_t u;
    asm("cvt.rna.tf32.f32 %0, %1;" : "=r"(u) : "f"(x));
    return __uint_as_float(u);
}

// ---------------------------------------------------------------------------
// 1. L2 normalize: one block (128 threads) per row. which = 0 -> vision->g_vn,
//    which = 1 -> text->g_tn. Output pre-rounded to tf32 so the tensor-core
//    GEMM sees exact tf32 bits (RNA rounding, better than HW truncation).
// ---------------------------------------------------------------------------
__global__ __launch_bounds__(128) void k_l2norm(const float* __restrict__ in,
                                                int D, int which) {
    __shared__ float sred[4];
    int row = blockIdx.x;
    float* out = which ? g_tn : g_vn;
    const float* r = in + (size_t)row * D;
    float* w = out + (size_t)row * D;
    float ss = 0.0f;
    for (int j = threadIdx.x * 4; j < D; j += 128 * 4) {
        float4 v = *(const float4*)&r[j];
        ss += v.x * v.x + v.y * v.y + v.z * v.z + v.w * v.w;
    }
    float tot = blockSum(ss, sred, 4);
    float inv = 1.0f / fmaxf(sqrtf(tot), 1e-12f);
    for (int j = threadIdx.x * 4; j < D; j += 128 * 4) {
        float4 v = *(const float4*)&r[j];
        v.x = to_tf32(v.x * inv); v.y = to_tf32(v.y * inv);
        v.z = to_tf32(v.z * inv); v.w = to_tf32(v.w * inv);
        *(float4*)&w[j] = v;
    }
}

// ---------------------------------------------------------------------------
// 2. Tensor-core GEMM NT (tf32): g_sim[i][j] = dot(g_vn_i, g_tn_j).
//    Block tile 128x128xK32, 8 warps in 2x4, warp tile 64x32 built from
//    mma.sync.m16n8k8 (4 m-subtiles x 4 n-subtiles). Smem [128][36] padding
//    gives conflict-free fragment loads and 16B-aligned float4 fills.
// ---------------------------------------------------------------------------
__global__ __launch_bounds__(256) void k_gemm_tf32(int N, int D) {
    __shared__ float As[128][36];
    __shared__ float Bs[128][36];
    const float* __restrict__ A = g_vn;
    const float* __restrict__ Bm = g_tn;
    int tid = threadIdx.x;
    int wid = tid >> 5, lane = tid & 31;
    int t4 = lane >> 2, tm4 = lane & 3;
    int mo = (wid >> 2) * 64;    // warp m offset: 0 or 64
    int no = (wid & 3) * 32;     // warp n offset: 0,32,64,96
    int row0 = blockIdx.y * 128, col0 = blockIdx.x * 128;

    float acc[4][4][4];
#pragma unroll
    for (int ms = 0; ms < 4; ms++)
#pragma unroll
        for (int ns = 0; ns < 4; ns++)
#pragma unroll
            for (int q = 0; q < 4; q++) acc[ms][ns][q] = 0.0f;

    for (int k0 = 0; k0 < D; k0 += 32) {
        // Fill As (rows of Vn) and Bs (rows of Tn), [row][k] layout.
#pragma unroll
        for (int q = 0; q < 4; q++) {
            int f = tid + q * 256;       // 0..1023 float4 slots
            int r = f >> 3;              // tile row 0..127
            int kc = (f & 7) << 2;       // k offset 0..28
            *(float4*)&As[r][kc] = *(const float4*)&A[(size_t)(row0 + r) * D + k0 + kc];
            *(float4*)&Bs[r][kc] = *(const float4*)&Bm[(size_t)(col0 + r) * D + k0 + kc];
        }
        __syncthreads();
#pragma unroll
        for (int kk = 0; kk < 32; kk += 8) {
            uint32_t a[4][4], b[4][2];
#pragma unroll
            for (int ms = 0; ms < 4; ms++) {
                int mr = mo + ms * 16 + t4;
                a[ms][0] = __float_as_uint(As[mr][kk + tm4]);
                a[ms][1] = __float_as_uint(As[mr + 8][kk + tm4]);
                a[ms][2] = __float_as_uint(As[mr][kk + tm4 + 4]);
                a[ms][3] = __float_as_uint(As[mr + 8][kk + tm4 + 4]);
            }
#pragma unroll
            for (int ns = 0; ns < 4; ns++) {
                int nr = no + ns * 8 + t4;
                b[ns][0] = __float_as_uint(Bs[nr][kk + tm4]);
                b[ns][1] = __float_as_uint(Bs[nr][kk + tm4 + 4]);
            }
#pragma unroll
            for (int ms = 0; ms < 4; ms++)
#pragma unroll
                for (int ns = 0; ns < 4; ns++)
                    asm volatile(
                        "mma.sync.aligned.m16n8k8.row.col.f32.tf32.tf32.f32 "
                        "{%0,%1,%2,%3}, {%4,%5,%6,%7}, {%8,%9}, {%0,%1,%2,%3};"
                        : "+f"(acc[ms][ns][0]), "+f"(acc[ms][ns][1]),
                          "+f"(acc[ms][ns][2]), "+f"(acc[ms][ns][3])
                        : "r"(a[ms][0]), "r"(a[ms][1]), "r"(a[ms][2]), "r"(a[ms][3]),
                          "r"(b[ns][0]), "r"(b[ns][1]));
        }
        __syncthreads();
    }

    // Epilogue: c0/c1 at (row, 2*tm4), c2/c3 at (row+8, 2*tm4); float2 stores.
#pragma unroll
    for (int ms = 0; ms < 4; ms++) {
        int r0 = row0 + mo + ms * 16 + t4;
#pragma unroll
        for (int ns = 0; ns < 4; ns++) {
            int c = col0 + no + ns * 8 + 2 * tm4;
            *(float2*)&g_sim[(size_t)r0 * N + c] =
                make_float2(acc[ms][ns][0], acc[ms][ns][1]);
            *(float2*)&g_sim[(size_t)(r0 + 8) * N + c] =
                make_float2(acc[ms][ns][2], acc[ms][ns][3]);
        }
    }
}

// ---------------------------------------------------------------------------
// 3. Transpose g_sim -> g_simT (32x32 tiles, block 32x8)
// ---------------------------------------------------------------------------
__global__ __launch_bounds__(256) void k_transpose(int N) {
    __shared__ float tile[32][33];
    int x0 = blockIdx.x * 32, y0 = blockIdx.y * 32;
    int tx = threadIdx.x, ty = threadIdx.y;
#pragma unroll
    for (int j = 0; j < 4; j++)
        tile[ty + 8 * j][tx] = g_sim[(size_t)(y0 + ty + 8 * j) * N + x0 + tx];
    __syncthreads();
#pragma unroll
    for (int j = 0; j < 4; j++)
        g_simT[(size_t)(x0 + ty + 8 * j) * N + y0 + tx] = tile[tx][ty + 8 * j];
}

// ---------------------------------------------------------------------------
// 4. Directional loss: one block (256 threads) per anchor row.
//    dir = 0: read g_sim, write g_lossA and g_cnt
//    dir = 1: read g_simT, write g_lossB
// ---------------------------------------------------------------------------
__global__ __launch_bounds__(256) void k_loss(const void* __restrict__ ids,
                                              int N, int dir) {
    __shared__ float s_sim[BMAX];
    __shared__ unsigned char s_m[BMAX];
    __shared__ float sred[8];

    const float* sim = dir ? g_simT : g_sim;
    int row = blockIdx.x;
    int mode = g_idmode;
    long long myid = load_id(ids, row, mode);
    int tid = threadIdx.x;

    // Pass 1: load row into smem, build match mask, positive sum & count
    float psum = 0.0f, pcnt = 0.0f;
    for (int j = tid; j < N; j += 256) {
        float s = sim[(size_t)row * N + j];
        s_sim[j] = s;
        bool m = (load_id(ids, j, mode) == myid);
        s_m[j] = (unsigned char)m;
        if (m) { psum += s; pcnt += 1.0f; }
    }
    float psumT = blockSum(psum, sred, 8);
    float pcntT = blockSum(pcnt, sred, 8);
    float mean_pos = psumT / fmaxf(pcntT, 1.0f);

    // Pass 2: weighted negative exp sum (semi-hard negatives get weight 2)
    float neg = 0.0f;
    float lo = mean_pos - MARGIN;
    for (int j = tid; j < N; j += 256) {
        if (!s_m[j]) {
            float s = s_sim[j];
            float w = (s < mean_pos && s > lo) ? 2.0f : 1.0f;
            neg += __expf(s * TEMP_INV) * w;
        }
    }
    float negT = blockSum(neg, sred, 8);

    // Pass 3: per-positive loss terms: log1p(neg * exp(-s/T)) ==
    //         -log(exp(s/T) / (exp(s/T) + neg))   (numerically stable)
    float lsum = 0.0f;
    for (int j = tid; j < N; j += 256) {
        if (s_m[j]) lsum += log1pf(negT * __expf(-s_sim[j] * TEMP_INV));
    }
    float lsumT = blockSum(lsum, sred, 8);

    if (tid == 0) {
        // valid_row: has positives AND has at least one negative
        bool valid = (pcntT > 0.5f) && (pcntT < (float)N - 0.5f);
        float r = valid ? lsumT : 0.0f;
        if (dir == 0) { g_lossA[row] = r; g_cnt[row] = pcntT; }
        else          { g_lossB[row] = r; }
    }
}

// ---------------------------------------------------------------------------
// 5. Finalize: single block reduces partials to scalar loss
// ---------------------------------------------------------------------------
__global__ __launch_bounds__(256) void k_finalize(float* __restrict__ out, int N) {
    __shared__ float sred[8];
    float a = 0.0f, b = 0.0f, c = 0.0f;
    for (int i = threadIdx.x; i < N; i += 256) {
        a += g_lossA[i];
        b += g_lossB[i];
        c += g_cnt[i];
    }
    float sa = blockSum(a, sred, 8);
    float sb = blockSum(b, sred, 8);
    float sc = blockSum(c, sred, 8);
    if (threadIdx.x == 0) {
        float loss = (sc > 0.0f) ? (sa + sb) / (2.0f * fmaxf(sc, 1.0f)) : 0.0f;
        out[0] = loss;
    }
}

// ---------------------------------------------------------------------------
// Launch: pure kernel launches only (graph-capture safe, allocation-free)
// ---------------------------------------------------------------------------
extern "C" void kernel_launch(void* const* d_in, const int* in_sizes, int n_in,
                              void* d_out, int out_size) {
    const float* vis = (const float*)d_in[0];
    const float* txt = (const float*)d_in[1];
    const void* ids = d_in[2];
    float* out = (float*)d_out;

    int B = in_sizes[2];
    int D = in_sizes[0] / B;
    if (B > BMAX) B = BMAX;
    if (D > DMAX) D = DMAX;

    k_detect<<<1, 256>>>((const int*)ids, B);

    k_l2norm<<<B, 128>>>(vis, D, 0);
    k_l2norm<<<B, 128>>>(txt, D, 1);

    dim3 ggrid(B / 128, B / 128);
    k_gemm_tf32<<<ggrid, 256>>>(B, D);

    dim3 tgrid(B / 32, B / 32);
    k_transpose<<<tgrid, dim3(32, 8)>>>(B);

    k_loss<<<B, 256>>>(ids, B, 0);
    k_loss<<<B, 256>>>(ids, B, 1);

    k_finalize<<<1, 256>>>(out, B);
}

// round 5
// speedup vs baseline: 2.9841x; 1.2094x over previous
#include <cuda_runtime.h>
#include <math.h>
#include <stdint.h>

// ---------------------------------------------------------------------------
// Problem constants (fixed instance: B=4096, D=512). Scratch lives in
// __device__ globals (no allocations allowed).
// ---------------------------------------------------------------------------
#define BMAX 4096
#define DMAX 512
#define TEMP_INV (1.0f / 0.07f)
#define MARGIN 0.2f

static __device__ float g_vn[BMAX * DMAX];                    // normalized vision (tf32)
static __device__ float g_tn[BMAX * DMAX];                    // normalized text (tf32)
static __device__ float g_sim[(size_t)BMAX * BMAX];           // sim = Vn Tn^T
static __device__ float g_simT[(size_t)BMAX * BMAX];          // sim^T
static __device__ float g_lossA[BMAX];                        // v2t per-row loss
static __device__ float g_lossB[BMAX];                        // t2v per-row loss
static __device__ float g_cnt[BMAX];                          // per-row positive count
static __device__ long long g_ids[BMAX];                      // normalized match ids

// ---------------------------------------------------------------------------
// Reductions
// ---------------------------------------------------------------------------
__device__ __forceinline__ float warpSum(float v) {
#pragma unroll
    for (int o = 16; o; o >>= 1) v += __shfl_down_sync(0xffffffffu, v, o);
    return v;
}

__device__ __forceinline__ float blockSum(float v, float* sred, int nwarp) {
    v = warpSum(v);
    int w = threadIdx.x >> 5, l = threadIdx.x & 31;
    if (l == 0) sred[w] = v;
    __syncthreads();
    if (threadIdx.x < 32) {
        float x = (l < nwarp) ? sred[l] : 0.0f;
        x = warpSum(x);
        if (l == 0) sred[0] = x;
    }
    __syncthreads();
    float r = sred[0];
    __syncthreads();
    return r;
}

// ---------------------------------------------------------------------------
// 0. Prep: detect match_ids dtype (int64 may have been downcast to int32 by
//    the jax pipeline) and normalize into g_ids[] as int64. If the buffer is
//    int64 with values < 2^31, all odd 32-bit words of the first n words are
//    zero; if int32, roughly half are nonzero.
// ---------------------------------------------------------------------------
__global__ __launch_bounds__(256) void k_prep(const int* __restrict__ w, int n) {
    __shared__ int flag;
    if (threadIdx.x == 0) flag = 0;
    __syncthreads();
    for (int j = threadIdx.x * 2 + 1; j < n; j += 512)
        if (w[j] != 0) flag = 1;   // benign race: any writer sets 1
    __syncthreads();
    int mode = flag ? 0 : 1;       // 0 = int32, 1 = int64
    for (int j = threadIdx.x; j < n; j += 256)
        g_ids[j] = mode ? ((const long long*)w)[j] : (long long)w[j];
}

// ---------------------------------------------------------------------------
// tf32 round-to-nearest helper
// ---------------------------------------------------------------------------
__device__ __forceinline__ float to_tf32(float x) {
    uint32_t u;
    asm("cvt.rna.tf32.f32 %0, %1;" : "=r"(u) : "f"(x));
    return __uint_as_float(u);
}

// ---------------------------------------------------------------------------
// 1. L2 normalize: one block (128 threads) per row, output tf32-rounded.
// ---------------------------------------------------------------------------
__global__ __launch_bounds__(128) void k_l2norm(const float* __restrict__ in,
                                                int D, int which) {
    __shared__ float sred[4];
    int row = blockIdx.x;
    float* out = which ? g_tn : g_vn;
    const float* r = in + (size_t)row * D;
    float* w = out + (size_t)row * D;
    float ss = 0.0f;
    for (int j = threadIdx.x * 4; j < D; j += 128 * 4) {
        float4 v = *(const float4*)&r[j];
        ss += v.x * v.x + v.y * v.y + v.z * v.z + v.w * v.w;
    }
    float tot = blockSum(ss, sred, 4);
    float inv = 1.0f / fmaxf(sqrtf(tot), 1e-12f);
    for (int j = threadIdx.x * 4; j < D; j += 128 * 4) {
        float4 v = *(const float4*)&r[j];
        v.x = to_tf32(v.x * inv); v.y = to_tf32(v.y * inv);
        v.z = to_tf32(v.z * inv); v.w = to_tf32(v.w * inv);
        *(float4*)&w[j] = v;
    }
}

// ---------------------------------------------------------------------------
// 2. Tensor-core GEMM NT (tf32) with cp.async double buffering + fused
//    transpose epilogue. Block tile 128x128xK32, 8 warps (2x4), warp tile
//    64x32 of m16n8k8 MMAs. Dynamic smem:
//      mainloop: As[2][128][36] | Bs[2][128][36]   (73728 B)
//      epilogue: tr[128][129]                      (66048 B, aliased)
// ---------------------------------------------------------------------------
#define SM_STRIDE 36
#define SM_STAGE  (128 * SM_STRIDE)
#define GEMM_SMEM_BYTES (4 * SM_STAGE * 4)   // 2 stages x 2 matrices

__device__ __forceinline__ void cp16(float* dst, const float* src) {
    uint32_t d = (uint32_t)__cvta_generic_to_shared(dst);
    asm volatile("cp.async.cg.shared.global [%0], [%1], 16;" :: "r"(d), "l"(src));
}

__global__ __launch_bounds__(256, 2) void k_gemm_tf32(int N, int D) {
    extern __shared__ float sm[];
    float* As = sm;                    // [2][128][36]
    float* Bs = sm + 2 * SM_STAGE;     // [2][128][36]
    float* tr = sm;                    // [128][129] (epilogue alias)

    const float* __restrict__ A = g_vn;
    const float* __restrict__ Bm = g_tn;
    int tid = threadIdx.x;
    int wid = tid >> 5, lane = tid & 31;
    int t4 = lane >> 2, tm4 = lane & 3;
    int mo = (wid >> 2) * 64;    // warp m offset: 0 or 64
    int no = (wid & 3) * 32;     // warp n offset: 0,32,64,96
    int row0 = blockIdx.y * 128, col0 = blockIdx.x * 128;

    // Per-thread load slots (4 float4 per matrix per tile)
    int lr[4], lk[4];
#pragma unroll
    for (int q = 0; q < 4; q++) {
        int f = tid + q * 256;
        lr[q] = f >> 3;
        lk[q] = (f & 7) << 2;
    }

    float acc[4][4][4];
#pragma unroll
    for (int ms = 0; ms < 4; ms++)
#pragma unroll
        for (int ns = 0; ns < 4; ns++)
#pragma unroll
            for (int q = 0; q < 4; q++) acc[ms][ns][q] = 0.0f;

    const int KT = D >> 5;   // 32-wide k tiles

    // Prologue: async-load tile 0 into stage 0
#pragma unroll
    for (int q = 0; q < 4; q++) {
        cp16(&As[lr[q] * SM_STRIDE + lk[q]], &A[(size_t)(row0 + lr[q]) * D + lk[q]]);
        cp16(&Bs[lr[q] * SM_STRIDE + lk[q]], &Bm[(size_t)(col0 + lr[q]) * D + lk[q]]);
    }
    asm volatile("cp.async.commit_group;");

    for (int kt = 0; kt < KT; kt++) {
        int cur = kt & 1;
        if (kt + 1 < KT) {
            int nxt = (kt + 1) & 1;
            int kb = (kt + 1) << 5;
#pragma unroll
            for (int q = 0; q < 4; q++) {
                cp16(&As[nxt * SM_STAGE + lr[q] * SM_STRIDE + lk[q]],
                     &A[(size_t)(row0 + lr[q]) * D + kb + lk[q]]);
                cp16(&Bs[nxt * SM_STAGE + lr[q] * SM_STRIDE + lk[q]],
                     &Bm[(size_t)(col0 + lr[q]) * D + kb + lk[q]]);
            }
            asm volatile("cp.async.commit_group;");
            asm volatile("cp.async.wait_group 1;");
        } else {
            asm volatile("cp.async.wait_group 0;");
        }
        __syncthreads();

        const float* Ac = As + cur * SM_STAGE;
        const float* Bc = Bs + cur * SM_STAGE;
#pragma unroll
        for (int kk = 0; kk < 32; kk += 8) {
            uint32_t a[4][4], b[4][2];
#pragma unroll
            for (int ms = 0; ms < 4; ms++) {
                int mr = mo + ms * 16 + t4;
                a[ms][0] = __float_as_uint(Ac[mr * SM_STRIDE + kk + tm4]);
                a[ms][1] = __float_as_uint(Ac[(mr + 8) * SM_STRIDE + kk + tm4]);
                a[ms][2] = __float_as_uint(Ac[mr * SM_STRIDE + kk + tm4 + 4]);
                a[ms][3] = __float_as_uint(Ac[(mr + 8) * SM_STRIDE + kk + tm4 + 4]);
            }
#pragma unroll
            for (int ns = 0; ns < 4; ns++) {
                int nr = no + ns * 8 + t4;
                b[ns][0] = __float_as_uint(Bc[nr * SM_STRIDE + kk + tm4]);
                b[ns][1] = __float_as_uint(Bc[nr * SM_STRIDE + kk + tm4 + 4]);
            }
#pragma unroll
            for (int ms = 0; ms < 4; ms++)
#pragma unroll
                for (int ns = 0; ns < 4; ns++)
                    asm volatile(
                        "mma.sync.aligned.m16n8k8.row.col.f32.tf32.tf32.f32 "
                        "{%0,%1,%2,%3}, {%4,%5,%6,%7}, {%8,%9}, {%0,%1,%2,%3};"
                        : "+f"(acc[ms][ns][0]), "+f"(acc[ms][ns][1]),
                          "+f"(acc[ms][ns][2]), "+f"(acc[ms][ns][3])
                        : "r"(a[ms][0]), "r"(a[ms][1]), "r"(a[ms][2]), "r"(a[ms][3]),
                          "r"(b[ns][0]), "r"(b[ns][1]));
        }
        __syncthreads();
    }

    // Epilogue: write g_sim directly from regs; stage tile in smem (aliasing
    // the stage buffers — mainloop fully done) for coalesced transposed write.
#pragma unroll
    for (int ms = 0; ms < 4; ms++) {
        int r_lo = mo + ms * 16 + t4;
#pragma unroll
        for (int ns = 0; ns < 4; ns++) {
            int c = no + ns * 8 + 2 * tm4;
            *(float2*)&g_sim[(size_t)(row0 + r_lo) * N + col0 + c] =
                make_float2(acc[ms][ns][0], acc[ms][ns][1]);
            *(float2*)&g_sim[(size_t)(row0 + r_lo + 8) * N + col0 + c] =
                make_float2(acc[ms][ns][2], acc[ms][ns][3]);
            tr[r_lo * 129 + c]       = acc[ms][ns][0];
            tr[r_lo * 129 + c + 1]   = acc[ms][ns][1];
            tr[(r_lo + 8) * 129 + c]     = acc[ms][ns][2];
            tr[(r_lo + 8) * 129 + c + 1] = acc[ms][ns][3];
        }
    }
    __syncthreads();
    // g_simT[col0+c][row0+r] = tile[r][c]; consecutive tid -> consecutive r.
#pragma unroll
    for (int i = 0; i < 64; i++) {
        int idx = tid + i * 256;
        int c = idx >> 7, r = idx & 127;
        g_simT[(size_t)(col0 + c) * N + row0 + r] = tr[r * 129 + c];
    }
}

// ---------------------------------------------------------------------------
// 3. Directional loss: one block per (anchor row, dir). dir = blockIdx.y:
//    0 -> g_sim rows, write g_lossA + g_cnt; 1 -> g_simT rows, write g_lossB.
// ---------------------------------------------------------------------------
__global__ __launch_bounds__(256) void k_loss(int N) {
    __shared__ float s_sim[BMAX];
    __shared__ unsigned char s_m[BMAX];
    __shared__ float sred[8];

    int dir = blockIdx.y;
    const float* sim = dir ? g_simT : g_sim;
    int row = blockIdx.x;
    long long myid = g_ids[row];
    int tid = threadIdx.x;

    // Pass 1: load row into smem, build match mask, positive sum & count
    float psum = 0.0f, pcnt = 0.0f;
    for (int j = tid; j < N; j += 256) {
        float s = sim[(size_t)row * N + j];
        s_sim[j] = s;
        bool m = (g_ids[j] == myid);
        s_m[j] = (unsigned char)m;
        if (m) { psum += s; pcnt += 1.0f; }
    }
    float psumT = blockSum(psum, sred, 8);
    float pcntT = blockSum(pcnt, sred, 8);
    float mean_pos = psumT / fmaxf(pcntT, 1.0f);

    // Pass 2: weighted negative exp sum (semi-hard negatives get weight 2)
    float neg = 0.0f;
    float lo = mean_pos - MARGIN;
    for (int j = tid; j < N; j += 256) {
        if (!s_m[j]) {
            float s = s_sim[j];
            float w = (s < mean_pos && s > lo) ? 2.0f : 1.0f;
            neg += __expf(s * TEMP_INV) * w;
        }
    }
    float negT = blockSum(neg, sred, 8);

    // Pass 3: per-positive loss terms: log1p(neg * exp(-s/T)) ==
    //         -log(exp(s/T) / (exp(s/T) + neg))   (numerically stable)
    float lsum = 0.0f;
    for (int j = tid; j < N; j += 256) {
        if (s_m[j]) lsum += log1pf(negT * __expf(-s_sim[j] * TEMP_INV));
    }
    float lsumT = blockSum(lsum, sred, 8);

    if (tid == 0) {
        // valid_row: has positives AND has at least one negative
        bool valid = (pcntT > 0.5f) && (pcntT < (float)N - 0.5f);
        float r = valid ? lsumT : 0.0f;
        if (dir == 0) { g_lossA[row] = r; g_cnt[row] = pcntT; }
        else          { g_lossB[row] = r; }
    }
}

// ---------------------------------------------------------------------------
// 4. Finalize: single block reduces partials to scalar loss
// ---------------------------------------------------------------------------
__global__ __launch_bounds__(256) void k_finalize(float* __restrict__ out, int N) {
    __shared__ float sred[8];
    float a = 0.0f, b = 0.0f, c = 0.0f;
    for (int i = threadIdx.x; i < N; i += 256) {
        a += g_lossA[i];
        b += g_lossB[i];
        c += g_cnt[i];
    }
    float sa = blockSum(a, sred, 8);
    float sb = blockSum(b, sred, 8);
    float sc = blockSum(c, sred, 8);
    if (threadIdx.x == 0) {
        float loss = (sc > 0.0f) ? (sa + sb) / (2.0f * fmaxf(sc, 1.0f)) : 0.0f;
        out[0] = loss;
    }
}

// ---------------------------------------------------------------------------
// Launch: kernel launches only (graph-capture safe, allocation-free).
// cudaFuncSetAttribute is a host-side attribute set (not a stream op).
// ---------------------------------------------------------------------------
extern "C" void kernel_launch(void* const* d_in, const int* in_sizes, int n_in,
                              void* d_out, int out_size) {
    const float* vis = (const float*)d_in[0];
    const float* txt = (const float*)d_in[1];
    const void* ids = d_in[2];
    float* out = (float*)d_out;

    int B = in_sizes[2];
    int D = in_sizes[0] / B;
    if (B > BMAX) B = BMAX;
    if (D > DMAX) D = DMAX;

    cudaFuncSetAttribute(k_gemm_tf32,
                         cudaFuncAttributeMaxDynamicSharedMemorySize,
                         GEMM_SMEM_BYTES);

    k_prep<<<1, 256>>>((const int*)ids, B);

    k_l2norm<<<B, 128>>>(vis, D, 0);
    k_l2norm<<<B, 128>>>(txt, D, 1);

    dim3 ggrid(B / 128, B / 128);
    k_gemm_tf32<<<ggrid, 256, GEMM_SMEM_BYTES>>>(B, D);

    dim3 lgrid(B, 2);
    k_loss<<<lgrid, 256>>>(B);

    k_finalize<<<1, 256>>>(out, B);
}